// round 2
// baseline (speedup 1.0000x reference)
#include <cuda_runtime.h>

#define Nn 50000
#define Ee 800000
#define HD 256

// ---------------- scratch (device globals; no runtime allocation) ----------
__device__ float g_feat[(size_t)Nn * HD];   // [N,256]
__device__ float g_el[Nn * 8];
__device__ float g_er[Nn * 8];
__device__ float g_ef1[(size_t)Ee * 32];    // [E,32]
__device__ float g_q[(size_t)Ee * 8];       // p * ee
__device__ float g_esum[Nn * 8];

__device__ __forceinline__ float ssp(float x) {
    // softplus(x) - ln2, numerically stable
    float e = __expf(-fabsf(x));
    return fmaxf(x, 0.f) + __logf(1.f + e) - 0.69314718056f;
}

// ---------------- K0: init output with bias, zero esum ---------------------
__global__ void k_init(float* __restrict__ out, const float* __restrict__ bias) {
    int stride = gridDim.x * blockDim.x;
    for (int i = blockIdx.x * blockDim.x + threadIdx.x; i < Nn * HD; i += stride)
        out[i] = bias[i & 255];
    for (int j = blockIdx.x * blockDim.x + threadIdx.x; j < Nn * 8; j += stride)
        g_esum[j] = 0.f;
}

// ---------------- K1: feat = nfeat @ W_fc^T  (GEMM_NT 50000x256x128) -------
__global__ void __launch_bounds__(256) k_feat(const float* __restrict__ A,
                                              const float* __restrict__ B) {
    __shared__ float As[16][68];   // [k][m], padded
    __shared__ float Bs[16][68];   // [k][n], padded (16B-aligned rows)
    int m0 = blockIdx.x * 64, n0 = blockIdx.y * 64;
    int t = threadIdx.x;
    int tx = t & 15, ty = t >> 4;
    int lr = t >> 2;            // 0..63
    int lc = (t & 3) * 4;       // k offset within chunk
    float acc[4][4];
#pragma unroll
    for (int i = 0; i < 4; i++)
#pragma unroll
        for (int j = 0; j < 4; j++) acc[i][j] = 0.f;

    for (int k0 = 0; k0 < 128; k0 += 16) {
        float4 av = make_float4(0.f, 0.f, 0.f, 0.f);
        int gm = m0 + lr;
        if (gm < Nn) av = *(const float4*)&A[gm * 128 + k0 + lc];
        As[lc + 0][lr] = av.x; As[lc + 1][lr] = av.y;
        As[lc + 2][lr] = av.z; As[lc + 3][lr] = av.w;
        float4 bv = *(const float4*)&B[(n0 + lr) * 128 + k0 + lc];
        Bs[lc + 0][lr] = bv.x; Bs[lc + 1][lr] = bv.y;
        Bs[lc + 2][lr] = bv.z; Bs[lc + 3][lr] = bv.w;
        __syncthreads();
#pragma unroll
        for (int kk = 0; kk < 16; kk++) {
            float a[4];
            float4 b4 = *(float4*)&Bs[kk][tx * 4];
#pragma unroll
            for (int i = 0; i < 4; i++) a[i] = As[kk][ty * 4 + i];
#pragma unroll
            for (int i = 0; i < 4; i++) {
                acc[i][0] += a[i] * b4.x; acc[i][1] += a[i] * b4.y;
                acc[i][2] += a[i] * b4.z; acc[i][3] += a[i] * b4.w;
            }
        }
        __syncthreads();
    }
#pragma unroll
    for (int i = 0; i < 4; i++) {
        int m = m0 + ty * 4 + i;
        if (m < Nn) {
#pragma unroll
            for (int j = 0; j < 4; j++)
                g_feat[(size_t)m * 256 + n0 + tx * 4 + j] = acc[i][j];
        }
    }
}

// ---------------- K1b: el/er per node (warp per node) ----------------------
__global__ void k_elr(const float* __restrict__ attn_l, const float* __restrict__ attn_r) {
    int warp = (blockIdx.x * blockDim.x + threadIdx.x) >> 5;
    int lane = threadIdx.x & 31;
    if (warp >= Nn) return;
#pragma unroll
    for (int h = 0; h < 8; h++) {
        float v = g_feat[(size_t)warp * 256 + h * 32 + lane];
        float pl = v * attn_l[h * 32 + lane];
        float pr = v * attn_r[h * 32 + lane];
#pragma unroll
        for (int s = 16; s; s >>= 1) {
            pl += __shfl_xor_sync(0xffffffffu, pl, s);
            pr += __shfl_xor_sync(0xffffffffu, pr, s);
        }
        if (lane == 0) { g_el[warp * 8 + h] = pl; g_er[warp * 8 + h] = pr; }
    }
}

// ---------------- K2: ef1 = ssp(efeat @ W_e1^T + b)  (800000x32x128) -------
// K-tiled: A staged in two 64-wide chunks to stay under the 48KB static limit.
__global__ void __launch_bounds__(256) k_ef1(const float* __restrict__ Eg,
                                             const float* __restrict__ W,
                                             const float* __restrict__ b) {
    __shared__ float As[64 * 68];   // [row][k-chunk], padded stride 68 (~17.4KB)
    __shared__ float Bs[128 * 36];  // [k][col], padded 36 (~18.4KB)
    __shared__ float sb1[32];
    int m0 = blockIdx.x * 64;
    int t = threadIdx.x;
    if (t < 32) sb1[t] = b[t];
    // stage W transposed (full K=128)
    for (int i = t; i < 1024; i += 256) {
        int n = i >> 5, k4 = (i & 31) * 4;
        float4 v = *(const float4*)&W[n * 128 + k4];
        Bs[(k4 + 0) * 36 + n] = v.x; Bs[(k4 + 1) * 36 + n] = v.y;
        Bs[(k4 + 2) * 36 + n] = v.z; Bs[(k4 + 3) * 36 + n] = v.w;
    }

    int tx = t & 15, ty = t >> 4;
    float acc[4][2];
#pragma unroll
    for (int i = 0; i < 4; i++) { acc[i][0] = 0.f; acc[i][1] = 0.f; }

    for (int k0 = 0; k0 < 128; k0 += 64) {
        __syncthreads();
        // stage A chunk: 64 rows x 64 k = 1024 float4 / 256 threads = 4 each
        for (int i = t; i < 1024; i += 256) {
            int r = i >> 4, k4 = (i & 15) * 4;
            float4 v = *(const float4*)&Eg[(size_t)(m0 + r) * 128 + k0 + k4];
            *(float4*)&As[r * 68 + k4] = v;
        }
        __syncthreads();
#pragma unroll 4
        for (int kk = 0; kk < 64; kk += 4) {
            float4 a[4];
#pragma unroll
            for (int i = 0; i < 4; i++) a[i] = *(float4*)&As[(ty * 4 + i) * 68 + kk];
#pragma unroll
            for (int k2 = 0; k2 < 4; k2++) {
                float2 bb = *(float2*)&Bs[(k0 + kk + k2) * 36 + tx * 2];
#pragma unroll
                for (int i = 0; i < 4; i++) {
                    float av = (&a[i].x)[k2];
                    acc[i][0] += av * bb.x; acc[i][1] += av * bb.y;
                }
            }
        }
    }
#pragma unroll
    for (int i = 0; i < 4; i++) {
        int row = m0 + ty * 4 + i;
#pragma unroll
        for (int j = 0; j < 2; j++) {
            int n = tx * 2 + j;
            g_ef1[(size_t)row * 32 + n] = ssp(acc[i][j] + sb1[n]);
        }
    }
}

// ---------------- K3: per-edge fused MLP2 + ee + exp-logit -----------------
// warp handles 8 edges at a time; lane owns outputs {lane*4+u} and {128+lane*4+u}
__global__ void __launch_bounds__(256) k_edge(const float* __restrict__ rij,
                                              const int* __restrict__ src,
                                              const int* __restrict__ dst,
                                              const float* __restrict__ W2,
                                              const float* __restrict__ b2,
                                              const float* __restrict__ attn_e) {
    __shared__ float WT[32 * 260];   // [k][o], padded row stride 260 (16B aligned)
    __shared__ float sb2[256], sae[256];
    __shared__ float sef[8][256];    // [warp][8 edges * 32]
    int t = threadIdx.x;
    for (int i = t; i < 8192; i += 256) {
        int o = i >> 5, k = i & 31;
        WT[k * 260 + o] = W2[i];
    }
    sb2[t] = b2[t];
    sae[t] = attn_e[t];
    __syncthreads();

    int wid = t >> 5, lane = t & 31;
    int warp_g = blockIdx.x * 8 + wid;
    int nwarps = gridDim.x * 8;

    for (int e0 = warp_g * 8; e0 < Ee; e0 += nwarps * 8) {
        __syncwarp();
#pragma unroll
        for (int le = 0; le < 8; le++)
            sef[wid][le * 32 + lane] = g_ef1[(size_t)(e0 + le) * 32 + lane];
        __syncwarp();

        float acc[8][8];
#pragma unroll
        for (int le = 0; le < 8; le++)
#pragma unroll
            for (int u = 0; u < 8; u++) acc[le][u] = 0.f;

#pragma unroll
        for (int k = 0; k < 32; k++) {
            float4 w0 = *(float4*)&WT[k * 260 + lane * 4];
            float4 w1 = *(float4*)&WT[k * 260 + 128 + lane * 4];
#pragma unroll
            for (int le = 0; le < 8; le++) {
                float a = sef[wid][le * 32 + k];
                acc[le][0] += a * w0.x; acc[le][1] += a * w0.y;
                acc[le][2] += a * w0.z; acc[le][3] += a * w0.w;
                acc[le][4] += a * w1.x; acc[le][5] += a * w1.y;
                acc[le][6] += a * w1.z; acc[le][7] += a * w1.w;
            }
        }

#pragma unroll
        for (int le = 0; le < 8; le++) {
            int e = e0 + le;
            float r = rij[e];
            float cw = (r < 5.f) ? 0.5f * (__cosf(0.62831853072f * r) + 1.f) : 0.f;
            float p1 = 0.f, p2 = 0.f;
#pragma unroll
            for (int u = 0; u < 4; u++) {
                int o1 = lane * 4 + u;
                int o2 = o1 + 128;
                p1 += ssp(acc[le][u] + sb2[o1]) * sae[o1];
                p2 += ssp(acc[le][4 + u] + sb2[o2]) * sae[o2];
            }
            p1 *= cw; p2 *= cw;
#pragma unroll
            for (int s = 1; s < 8; s <<= 1) {
                p1 += __shfl_xor_sync(0xffffffffu, p1, s);
                p2 += __shfl_xor_sync(0xffffffffu, p2, s);
            }
            if ((lane & 7) == 0) {
                int sN = src[e], dN = dst[e];
                int h1 = lane >> 3;
                int h2 = h1 + 4;
                float l1 = g_el[sN * 8 + h1] + g_er[dN * 8 + h1] + p1;
                float l2 = g_el[sN * 8 + h2] + g_er[dN * 8 + h2] + p2;
                l1 = (l1 > 0.f) ? l1 : 0.2f * l1;
                l2 = (l2 > 0.f) ? l2 : 0.2f * l2;
                float pp1 = __expf(l1);
                float pp2 = __expf(l2);
                g_q[(size_t)e * 8 + h1] = pp1 * p1;
                g_q[(size_t)e * 8 + h2] = pp2 * p2;
                atomicAdd(&g_esum[dN * 8 + h1], pp1);
                atomicAdd(&g_esum[dN * 8 + h2], pp2);
            }
        }
    }
}

// ---------------- K4: aggregation out[dst] += feat[src] * c ----------------
__global__ void __launch_bounds__(256) k_agg(const int* __restrict__ src,
                                             const int* __restrict__ dst,
                                             float* __restrict__ out) {
    int t = threadIdx.x;
    int wid = t >> 5, lane = t & 31;
    int e = blockIdx.x * 8 + wid;
    if (e >= Ee) return;
    int s = src[e], d = dst[e];
    float c = 0.f;
    if (lane < 8) {
        float sum = g_esum[d * 8 + lane];        // > 0: this edge contributed
        c = g_q[(size_t)e * 8 + lane] / sum;
    }
    const float4* fsrc = (const float4*)&g_feat[(size_t)s * 256];
    float* obase = &out[(size_t)d * 256];
#pragma unroll
    for (int i = 0; i < 2; i++) {
        int s4 = i * 32 + lane;                  // float4 slot, h = s4>>3
        float cc = __shfl_sync(0xffffffffu, c, s4 >> 3);
        float4 f = fsrc[s4];
        float* addr = obase + s4 * 4;
        asm volatile("red.global.add.v4.f32 [%0], {%1, %2, %3, %4};"
                     :: "l"(addr), "f"(f.x * cc), "f"(f.y * cc),
                        "f"(f.z * cc), "f"(f.w * cc)
                     : "memory");
    }
}

// ---------------- launch ----------------------------------------------------
extern "C" void kernel_launch(void* const* d_in, const int* in_sizes, int n_in,
                              void* d_out, int out_size) {
    const float* nfeat  = (const float*)d_in[0];
    const float* efeat  = (const float*)d_in[1];
    const float* rij    = (const float*)d_in[2];
    const int*   src    = (const int*)d_in[3];
    const int*   dst    = (const int*)d_in[4];
    const float* W_fc   = (const float*)d_in[5];
    const float* W_e1   = (const float*)d_in[6];
    const float* b_e1   = (const float*)d_in[7];
    const float* W_e2   = (const float*)d_in[8];
    const float* b_e2   = (const float*)d_in[9];
    const float* attn_l = (const float*)d_in[10];
    const float* attn_r = (const float*)d_in[11];
    const float* attn_e = (const float*)d_in[12];
    const float* bias   = (const float*)d_in[13];
    float* out = (float*)d_out;

    k_init<<<2048, 256>>>(out, bias);
    k_feat<<<dim3((Nn + 63) / 64, 4), 256>>>(nfeat, W_fc);
    k_elr<<<(Nn * 32) / 256, 256>>>(attn_l, attn_r);
    k_ef1<<<Ee / 64, 256>>>(efeat, W_e1, b_e1);
    k_edge<<<888, 256>>>(rij, src, dst, W_e2, b_e2, attn_e);
    k_agg<<<Ee / 8, 256>>>(src, dst, out);
}